// round 9
// baseline (speedup 1.0000x reference)
#include <cuda_runtime.h>
#include <cstdint>

// Problem dims
#define DIMC 2048
#define BB   8
#define TT   2048
#define MROWS 16384            // BB*TT
// NELEM = 16384*2048 = 33554432

// ---------------- scratch (static device globals; no dynamic alloc) ----------
__device__ float g_h [33554432];
__device__ float g_xr[33554432];
__device__ float g_xk[33554432];
__device__ float g_xv[33554432];
__device__ float g_r [33554432];
__device__ float g_k [33554432];
__device__ float g_v [33554432];

// ---------------- helpers ----------------------------------------------------
__device__ __forceinline__ uint32_t smem_u32(const void* p) {
    return (uint32_t)__cvta_generic_to_shared(p);
}
__device__ __forceinline__ void cp_async16(uint32_t saddr, const void* gptr) {
    asm volatile("cp.async.cg.shared.global [%0], [%1], 16;\n" :: "r"(saddr), "l"(gptr));
}
__device__ __forceinline__ float sigmoidf_(float x) {
    return 1.0f / (1.0f + expf(-x));
}

// ---------------- LayerNorm: one block per row (2048 cols) -------------------
__global__ __launch_bounds__(256) void ln_kernel(
    const float* __restrict__ x, const float* __restrict__ g,
    const float* __restrict__ b, float* __restrict__ out)
{
    __shared__ float sred[16];
    int row = blockIdx.x;
    int tid = threadIdx.x;
    const float4* xp = (const float4*)(x + (size_t)row * DIMC);
    float4 v0 = xp[tid];
    float4 v1 = xp[tid + 256];
    float s  = v0.x+v0.y+v0.z+v0.w + v1.x+v1.y+v1.z+v1.w;
    float ss = v0.x*v0.x+v0.y*v0.y+v0.z*v0.z+v0.w*v0.w
             + v1.x*v1.x+v1.y*v1.y+v1.z*v1.z+v1.w*v1.w;
    #pragma unroll
    for (int o = 16; o > 0; o >>= 1) {
        s  += __shfl_xor_sync(0xffffffffu, s,  o);
        ss += __shfl_xor_sync(0xffffffffu, ss, o);
    }
    int wid = tid >> 5;
    if ((tid & 31) == 0) { sred[wid] = s; sred[wid + 8] = ss; }
    __syncthreads();
    if (tid < 32) {
        float a = (tid < 8) ? sred[tid]     : 0.f;
        float c = (tid < 8) ? sred[tid + 8] : 0.f;
        #pragma unroll
        for (int o = 4; o > 0; o >>= 1) {
            a += __shfl_xor_sync(0xffffffffu, a, o);
            c += __shfl_xor_sync(0xffffffffu, c, o);
        }
        if (tid == 0) { sred[0] = a; sred[1] = c; }
    }
    __syncthreads();
    float mean = sred[0] * (1.0f / DIMC);
    float var  = sred[1] * (1.0f / DIMC) - mean * mean;
    float rstd = rsqrtf(var + 1e-5f);

    const float4* gp = (const float4*)g;
    const float4* bp = (const float4*)b;
    float4 g0 = gp[tid], g1 = gp[tid + 256];
    float4 b0 = bp[tid], b1 = bp[tid + 256];
    float4 o0, o1;
    o0.x = (v0.x - mean) * rstd * g0.x + b0.x;
    o0.y = (v0.y - mean) * rstd * g0.y + b0.y;
    o0.z = (v0.z - mean) * rstd * g0.z + b0.z;
    o0.w = (v0.w - mean) * rstd * g0.w + b0.w;
    o1.x = (v1.x - mean) * rstd * g1.x + b1.x;
    o1.y = (v1.y - mean) * rstd * g1.y + b1.y;
    o1.z = (v1.z - mean) * rstd * g1.z + b1.z;
    o1.w = (v1.w - mean) * rstd * g1.w + b1.w;
    float4* op = (float4*)(out + (size_t)row * DIMC);
    op[tid] = o0;
    op[tid + 256] = o1;
}

// ---------------- token-shift mixes ------------------------------------------
#define MIX4(o, mu, hv, hp)                          \
    o.x = mu.x * hv.x + (1.f - mu.x) * hp.x;         \
    o.y = mu.y * hv.y + (1.f - mu.y) * hp.y;         \
    o.z = mu.z * hv.z + (1.f - mu.z) * hp.z;         \
    o.w = mu.w * hv.w + (1.f - mu.w) * hp.w;

__global__ __launch_bounds__(256) void mix3_kernel(
    const float* __restrict__ h,
    const float* __restrict__ mur, const float* __restrict__ muk,
    const float* __restrict__ muv,
    float* __restrict__ xr, float* __restrict__ xk, float* __restrict__ xv)
{
    size_t i = (size_t)blockIdx.x * 256 + threadIdx.x;   // float4 index
    const float4* h4 = (const float4*)h;
    float4 hv = h4[i];
    int row = (int)(i >> 9);          // / (DIMC/4 = 512)
    int t = row & (TT - 1);
    float4 hp = make_float4(0.f, 0.f, 0.f, 0.f);
    if (t > 0) hp = h4[i - 512];
    int c4 = (int)(i & 511);
    float4 mr = ((const float4*)mur)[c4];
    float4 mk = ((const float4*)muk)[c4];
    float4 mv = ((const float4*)muv)[c4];
    float4 o;
    MIX4(o, mr, hv, hp); ((float4*)xr)[i] = o;
    MIX4(o, mk, hv, hp); ((float4*)xk)[i] = o;
    MIX4(o, mv, hv, hp); ((float4*)xv)[i] = o;
}

__global__ __launch_bounds__(256) void mix2_kernel(
    const float* __restrict__ h,
    const float* __restrict__ mur, const float* __restrict__ muk,
    float* __restrict__ xr, float* __restrict__ xk)
{
    size_t i = (size_t)blockIdx.x * 256 + threadIdx.x;
    const float4* h4 = (const float4*)h;
    float4 hv = h4[i];
    int row = (int)(i >> 9);
    int t = row & (TT - 1);
    float4 hp = make_float4(0.f, 0.f, 0.f, 0.f);
    if (t > 0) hp = h4[i - 512];
    int c4 = (int)(i & 511);
    float4 mr = ((const float4*)mur)[c4];
    float4 mk = ((const float4*)muk)[c4];
    float4 o;
    MIX4(o, mr, hv, hp); ((float4*)xr)[i] = o;
    MIX4(o, mk, hv, hp); ((float4*)xk)[i] = o;
}

// ---------------- wkv: z = sigmoid(r) * (e^{u+k} v)/(e^{u+k}+1e-8) -----------
__global__ __launch_bounds__(256) void wkv_kernel(
    const float* __restrict__ r, const float* __restrict__ k,
    const float* __restrict__ v, const float* __restrict__ u,
    float* __restrict__ z)
{
    size_t i = (size_t)blockIdx.x * 256 + threadIdx.x;
    float4 rv = ((const float4*)r)[i];
    float4 kv = ((const float4*)k)[i];
    float4 vv = ((const float4*)v)[i];
    int c4 = (int)(i & 511);
    float4 uv = ((const float4*)u)[c4];
    float4 o;
    {
        float ek = expf(uv.x + kv.x);
        o.x = sigmoidf_(rv.x) * (ek * vv.x) / (ek + 1e-8f);
    }
    {
        float ek = expf(uv.y + kv.y);
        o.y = sigmoidf_(rv.y) * (ek * vv.y) / (ek + 1e-8f);
    }
    {
        float ek = expf(uv.z + kv.z);
        o.z = sigmoidf_(rv.z) * (ek * vv.z) / (ek + 1e-8f);
    }
    {
        float ek = expf(uv.w + kv.w);
        o.w = sigmoidf_(rv.w) * (ek * vv.w) / (ek + 1e-8f);
    }
    ((float4*)z)[i] = o;
}

// ---------------- k2 = relu(k)^2 in place ------------------------------------
__global__ __launch_bounds__(256) void relusq_kernel(float* __restrict__ k)
{
    size_t i = (size_t)blockIdx.x * 256 + threadIdx.x;
    float4 kv = ((float4*)k)[i];
    float a = fmaxf(kv.x, 0.f), b = fmaxf(kv.y, 0.f);
    float c = fmaxf(kv.z, 0.f), d = fmaxf(kv.w, 0.f);
    kv.x = a * a; kv.y = b * b; kv.z = c * c; kv.w = d * d;
    ((float4*)k)[i] = kv;
}

// ---------------- TF32 GEMM: C[m,n] = sum_k A[m,k] * W[n,k] ------------------
// M=16384, N=2048, K=2048. Block tile 128x128x32, 8 warps, warp tile 32x64.
// SMEM: [A|B] x 2 stages, row stride 36 floats -> conflict-free fragment LDS.
// EPI 0: C = acc
// EPI 1: C = aux + acc                      (residual add of x)
// EPI 2: C = C + sigmoid(aux) * acc         (final channel-mix gate, in-place)

#define GSTR 36   // smem row stride in floats (36*4 = 144B, 16B aligned)

__device__ __forceinline__ void gemm_issue(
    const float* __restrict__ Abase, const float* __restrict__ Wbase,
    float* Asb, float* Bsb, int kofs, int tid)
{
    #pragma unroll
    for (int j = 0; j < 4; j++) {
        int ch = tid + j * 256;
        int r  = ch >> 3;
        int k4 = (ch & 7) * 4;
        cp_async16(smem_u32(Asb + r * GSTR + k4), Abase + (size_t)r * 2048 + kofs + k4);
        cp_async16(smem_u32(Bsb + r * GSTR + k4), Wbase + (size_t)r * 2048 + kofs + k4);
    }
    asm volatile("cp.async.commit_group;\n" ::: "memory");
}

template<int EPI>
__global__ __launch_bounds__(256) void gemm_kernel(
    const float* __restrict__ A, const float* __restrict__ W,
    float* __restrict__ C, const float* __restrict__ aux)
{
    extern __shared__ float smem[];
    float* As = smem;                     // 2 stages * 128*GSTR
    float* Bs = smem + 2 * 128 * GSTR;

    int tid  = threadIdx.x;
    int lane = tid & 31;
    int wid  = tid >> 5;
    int bm = blockIdx.y * 128;
    int bn = blockIdx.x * 128;
    int mwarp = (wid & 3) * 32;
    int nwarp = (wid >> 2) * 64;

    const float* Abase = A + (size_t)bm * 2048;
    const float* Wbase = W + (size_t)bn * 2048;

    float acc[2][8][4];
    #pragma unroll
    for (int i = 0; i < 2; i++)
        #pragma unroll
        for (int j = 0; j < 8; j++)
            #pragma unroll
            for (int q = 0; q < 4; q++) acc[i][j][q] = 0.f;

    gemm_issue(Abase, Wbase, As, Bs, 0, tid);

    const int NC = 2048 / 32;   // 64 k-chunks
    for (int c = 0; c < NC; c++) {
        int buf = c & 1;
        if (c + 1 < NC) {
            gemm_issue(Abase, Wbase,
                       As + (buf ^ 1) * 128 * GSTR,
                       Bs + (buf ^ 1) * 128 * GSTR,
                       (c + 1) * 32, tid);
            asm volatile("cp.async.wait_group 1;\n" ::: "memory");
        } else {
            asm volatile("cp.async.wait_group 0;\n" ::: "memory");
        }
        __syncthreads();

        const float* Asb = As + buf * 128 * GSTR;
        const float* Bsb = Bs + buf * 128 * GSTR;

        #pragma unroll
        for (int ks = 0; ks < 4; ks++) {
            int k0 = ks * 8 + (lane & 3);
            uint32_t a[2][4];
            #pragma unroll
            for (int mt = 0; mt < 2; mt++) {
                const float* p = Asb + (mwarp + mt * 16 + (lane >> 2)) * GSTR + k0;
                a[mt][0] = __float_as_uint(p[0]);
                a[mt][1] = __float_as_uint(p[8 * GSTR]);
                a[mt][2] = __float_as_uint(p[4]);
                a[mt][3] = __float_as_uint(p[8 * GSTR + 4]);
            }
            #pragma unroll
            for (int nt = 0; nt < 8; nt++) {
                const float* p = Bsb + (nwarp + nt * 8 + (lane >> 2)) * GSTR + k0;
                uint32_t b0 = __float_as_uint(p[0]);
                uint32_t b1 = __float_as_uint(p[4]);
                #pragma unroll
                for (int mt = 0; mt < 2; mt++) {
                    asm volatile(
                        "mma.sync.aligned.m16n8k8.row.col.f32.tf32.tf32.f32 "
                        "{%0,%1,%2,%3},{%4,%5,%6,%7},{%8,%9},{%0,%1,%2,%3};\n"
                        : "+f"(acc[mt][nt][0]), "+f"(acc[mt][nt][1]),
                          "+f"(acc[mt][nt][2]), "+f"(acc[mt][nt][3])
                        : "r"(a[mt][0]), "r"(a[mt][1]), "r"(a[mt][2]), "r"(a[mt][3]),
                          "r"(b0), "r"(b1));
                }
            }
        }
        __syncthreads();
    }

    // ---------------- epilogue ----------------
    int rbase = bm + mwarp + (lane >> 2);
    int cbase = bn + nwarp + (lane & 3) * 2;
    #pragma unroll
    for (int mt = 0; mt < 2; mt++) {
        #pragma unroll
        for (int nt = 0; nt < 8; nt++) {
            int r0 = rbase + mt * 16;
            int cc = cbase + nt * 8;
            size_t i0 = (size_t)r0 * 2048 + cc;
            size_t i1 = i0 + (size_t)8 * 2048;
            float v0 = acc[mt][nt][0], v1 = acc[mt][nt][1];
            float v2 = acc[mt][nt][2], v3 = acc[mt][nt][3];
            if (EPI == 0) {
                C[i0] = v0;  C[i0 + 1] = v1;
                C[i1] = v2;  C[i1 + 1] = v3;
            } else if (EPI == 1) {
                C[i0] = aux[i0] + v0;          C[i0 + 1] = aux[i0 + 1] + v1;
                C[i1] = aux[i1] + v2;          C[i1 + 1] = aux[i1 + 1] + v3;
            } else {
                C[i0]     = C[i0]     + sigmoidf_(aux[i0])     * v0;
                C[i0 + 1] = C[i0 + 1] + sigmoidf_(aux[i0 + 1]) * v1;
                C[i1]     = C[i1]     + sigmoidf_(aux[i1])     * v2;
                C[i1 + 1] = C[i1 + 1] + sigmoidf_(aux[i1 + 1]) * v3;
            }
        }
    }
}

// ---------------- host orchestration -----------------------------------------
extern "C" void kernel_launch(void* const* d_in, const int* in_sizes, int n_in,
                              void* d_out, int out_size)
{
    const float* x    = (const float*)d_in[0];
    const float* ln1g = (const float*)d_in[1];
    const float* ln1b = (const float*)d_in[2];
    const float* ln2g = (const float*)d_in[3];
    const float* ln2b = (const float*)d_in[4];
    // d_in[5] = tm_w (unused by the reference semantics)
    const float* tmu  = (const float*)d_in[6];
    const float* tmur = (const float*)d_in[7];
    const float* tmuk = (const float*)d_in[8];
    const float* tmuv = (const float*)d_in[9];
    const float* tWr  = (const float*)d_in[10];
    const float* tWk  = (const float*)d_in[11];
    const float* tWv  = (const float*)d_in[12];
    const float* tWo  = (const float*)d_in[13];
    const float* cmur = (const float*)d_in[14];
    const float* cmuk = (const float*)d_in[15];
    const float* cWr  = (const float*)d_in[16];
    const float* cWk  = (const float*)d_in[17];
    const float* cWv  = (const float*)d_in[18];
    float* out = (float*)d_out;

    float *h, *xr, *xk, *xv, *rr, *kk, *vv;
    cudaGetSymbolAddress((void**)&h,  g_h);
    cudaGetSymbolAddress((void**)&xr, g_xr);
    cudaGetSymbolAddress((void**)&xk, g_xk);
    cudaGetSymbolAddress((void**)&xv, g_xv);
    cudaGetSymbolAddress((void**)&rr, g_r);
    cudaGetSymbolAddress((void**)&kk, g_k);
    cudaGetSymbolAddress((void**)&vv, g_v);

    const int SMEM = 4 * 128 * GSTR * 4;   // 73728 B (2 stages A + B)
    cudaFuncSetAttribute(gemm_kernel<0>, cudaFuncAttributeMaxDynamicSharedMemorySize, SMEM);
    cudaFuncSetAttribute(gemm_kernel<1>, cudaFuncAttributeMaxDynamicSharedMemorySize, SMEM);
    cudaFuncSetAttribute(gemm_kernel<2>, cudaFuncAttributeMaxDynamicSharedMemorySize, SMEM);

    dim3 gg(16, 128);         // N tiles x M tiles
    const int EW = 32768;     // (16384*2048/4) / 256

    // ---- time mixing ----
    ln_kernel  <<<MROWS, 256>>>(x, ln1g, ln1b, h);
    mix3_kernel<<<EW, 256>>>(h, tmur, tmuk, tmuv, xr, xk, xv);
    gemm_kernel<0><<<gg, 256, SMEM>>>(xr, tWr, rr, nullptr);
    gemm_kernel<0><<<gg, 256, SMEM>>>(xk, tWk, kk, nullptr);
    gemm_kernel<0><<<gg, 256, SMEM>>>(xv, tWv, vv, nullptr);
    wkv_kernel <<<EW, 256>>>(rr, kk, vv, tmu, xr);          // z -> xr
    gemm_kernel<1><<<gg, 256, SMEM>>>(xr, tWo, out, x);     // x2 = x + z@Wout^T

    // ---- channel mixing ----
    ln_kernel  <<<MROWS, 256>>>(out, ln2g, ln2b, h);
    mix2_kernel<<<EW, 256>>>(h, cmur, cmuk, xr, xk);
    gemm_kernel<0><<<gg, 256, SMEM>>>(xr, cWr, rr, nullptr);  // r2 pre-sigmoid
    gemm_kernel<0><<<gg, 256, SMEM>>>(xk, cWk, kk, nullptr);  // k2 pre-relu^2
    relusq_kernel<<<EW, 256>>>(kk);
    gemm_kernel<2><<<gg, 256, SMEM>>>(kk, cWv, out, rr);      // out = x2 + sig(r2)*acc
}

// round 10
// speedup vs baseline: 1.0003x; 1.0003x over previous
#include <cuda_runtime.h>
#include <cstdint>

// Problem dims
#define DIMC 2048
#define BB   8
#define TT   2048
#define MROWS 16384            // BB*TT
// NELEM = 16384*2048 = 33554432

// ---------------- scratch (static device globals; no dynamic alloc) ----------
__device__ float g_h [33554432];
__device__ float g_xr[33554432];
__device__ float g_xk[33554432];
__device__ float g_xv[33554432];
__device__ float g_r [33554432];
__device__ float g_k [33554432];
__device__ float g_v [33554432];

// ---------------- helpers ----------------------------------------------------
__device__ __forceinline__ uint32_t smem_u32(const void* p) {
    return (uint32_t)__cvta_generic_to_shared(p);
}
__device__ __forceinline__ void cp_async16(uint32_t saddr, const void* gptr) {
    asm volatile("cp.async.cg.shared.global [%0], [%1], 16;\n" :: "r"(saddr), "l"(gptr));
}
__device__ __forceinline__ float sigmoidf_(float x) {
    return 1.0f / (1.0f + expf(-x));
}

// ---------------- LayerNorm: one block per row (2048 cols) -------------------
__global__ __launch_bounds__(256) void ln_kernel(
    const float* __restrict__ x, const float* __restrict__ g,
    const float* __restrict__ b, float* __restrict__ out)
{
    __shared__ float sred[16];
    int row = blockIdx.x;
    int tid = threadIdx.x;
    const float4* xp = (const float4*)(x + (size_t)row * DIMC);
    float4 v0 = xp[tid];
    float4 v1 = xp[tid + 256];
    float s  = v0.x+v0.y+v0.z+v0.w + v1.x+v1.y+v1.z+v1.w;
    float ss = v0.x*v0.x+v0.y*v0.y+v0.z*v0.z+v0.w*v0.w
             + v1.x*v1.x+v1.y*v1.y+v1.z*v1.z+v1.w*v1.w;
    #pragma unroll
    for (int o = 16; o > 0; o >>= 1) {
        s  += __shfl_xor_sync(0xffffffffu, s,  o);
        ss += __shfl_xor_sync(0xffffffffu, ss, o);
    }
    int wid = tid >> 5;
    if ((tid & 31) == 0) { sred[wid] = s; sred[wid + 8] = ss; }
    __syncthreads();
    if (tid < 32) {
        float a = (tid < 8) ? sred[tid]     : 0.f;
        float c = (tid < 8) ? sred[tid + 8] : 0.f;
        #pragma unroll
        for (int o = 4; o > 0; o >>= 1) {
            a += __shfl_xor_sync(0xffffffffu, a, o);
            c += __shfl_xor_sync(0xffffffffu, c, o);
        }
        if (tid == 0) { sred[0] = a; sred[1] = c; }
    }
    __syncthreads();
    float mean = sred[0] * (1.0f / DIMC);
    float var  = sred[1] * (1.0f / DIMC) - mean * mean;
    float rstd = rsqrtf(var + 1e-5f);

    const float4* gp = (const float4*)g;
    const float4* bp = (const float4*)b;
    float4 g0 = gp[tid], g1 = gp[tid + 256];
    float4 b0 = bp[tid], b1 = bp[tid + 256];
    float4 o0, o1;
    o0.x = (v0.x - mean) * rstd * g0.x + b0.x;
    o0.y = (v0.y - mean) * rstd * g0.y + b0.y;
    o0.z = (v0.z - mean) * rstd * g0.z + b0.z;
    o0.w = (v0.w - mean) * rstd * g0.w + b0.w;
    o1.x = (v1.x - mean) * rstd * g1.x + b1.x;
    o1.y = (v1.y - mean) * rstd * g1.y + b1.y;
    o1.z = (v1.z - mean) * rstd * g1.z + b1.z;
    o1.w = (v1.w - mean) * rstd * g1.w + b1.w;
    float4* op = (float4*)(out + (size_t)row * DIMC);
    op[tid] = o0;
    op[tid + 256] = o1;
}

// ---------------- token-shift mixes ------------------------------------------
#define MIX4(o, mu, hv, hp)                          \
    o.x = mu.x * hv.x + (1.f - mu.x) * hp.x;         \
    o.y = mu.y * hv.y + (1.f - mu.y) * hp.y;         \
    o.z = mu.z * hv.z + (1.f - mu.z) * hp.z;         \
    o.w = mu.w * hv.w + (1.f - mu.w) * hp.w;

__global__ __launch_bounds__(256) void mix3_kernel(
    const float* __restrict__ h,
    const float* __restrict__ mur, const float* __restrict__ muk,
    const float* __restrict__ muv,
    float* __restrict__ xr, float* __restrict__ xk, float* __restrict__ xv)
{
    size_t i = (size_t)blockIdx.x * 256 + threadIdx.x;   // float4 index
    const float4* h4 = (const float4*)h;
    float4 hv = h4[i];
    int row = (int)(i >> 9);          // / (DIMC/4 = 512)
    int t = row & (TT - 1);
    float4 hp = make_float4(0.f, 0.f, 0.f, 0.f);
    if (t > 0) hp = h4[i - 512];
    int c4 = (int)(i & 511);
    float4 mr = ((const float4*)mur)[c4];
    float4 mk = ((const float4*)muk)[c4];
    float4 mv = ((const float4*)muv)[c4];
    float4 o;
    MIX4(o, mr, hv, hp); ((float4*)xr)[i] = o;
    MIX4(o, mk, hv, hp); ((float4*)xk)[i] = o;
    MIX4(o, mv, hv, hp); ((float4*)xv)[i] = o;
}

__global__ __launch_bounds__(256) void mix2_kernel(
    const float* __restrict__ h,
    const float* __restrict__ mur, const float* __restrict__ muk,
    float* __restrict__ xr, float* __restrict__ xk)
{
    size_t i = (size_t)blockIdx.x * 256 + threadIdx.x;
    const float4* h4 = (const float4*)h;
    float4 hv = h4[i];
    int row = (int)(i >> 9);
    int t = row & (TT - 1);
    float4 hp = make_float4(0.f, 0.f, 0.f, 0.f);
    if (t > 0) hp = h4[i - 512];
    int c4 = (int)(i & 511);
    float4 mr = ((const float4*)mur)[c4];
    float4 mk = ((const float4*)muk)[c4];
    float4 o;
    MIX4(o, mr, hv, hp); ((float4*)xr)[i] = o;
    MIX4(o, mk, hv, hp); ((float4*)xk)[i] = o;
}

// ---------------- wkv: z = sigmoid(r) * (e^{u+k} v)/(e^{u+k}+1e-8) -----------
__global__ __launch_bounds__(256) void wkv_kernel(
    const float* __restrict__ r, const float* __restrict__ k,
    const float* __restrict__ v, const float* __restrict__ u,
    float* __restrict__ z)
{
    size_t i = (size_t)blockIdx.x * 256 + threadIdx.x;
    float4 rv = ((const float4*)r)[i];
    float4 kv = ((const float4*)k)[i];
    float4 vv = ((const float4*)v)[i];
    int c4 = (int)(i & 511);
    float4 uv = ((const float4*)u)[c4];
    float4 o;
    {
        float ek = expf(uv.x + kv.x);
        o.x = sigmoidf_(rv.x) * (ek * vv.x) / (ek + 1e-8f);
    }
    {
        float ek = expf(uv.y + kv.y);
        o.y = sigmoidf_(rv.y) * (ek * vv.y) / (ek + 1e-8f);
    }
    {
        float ek = expf(uv.z + kv.z);
        o.z = sigmoidf_(rv.z) * (ek * vv.z) / (ek + 1e-8f);
    }
    {
        float ek = expf(uv.w + kv.w);
        o.w = sigmoidf_(rv.w) * (ek * vv.w) / (ek + 1e-8f);
    }
    ((float4*)z)[i] = o;
}

// ---------------- k2 = relu(k)^2 in place ------------------------------------
__global__ __launch_bounds__(256) void relusq_kernel(float* __restrict__ k)
{
    size_t i = (size_t)blockIdx.x * 256 + threadIdx.x;
    float4 kv = ((float4*)k)[i];
    float a = fmaxf(kv.x, 0.f), b = fmaxf(kv.y, 0.f);
    float c = fmaxf(kv.z, 0.f), d = fmaxf(kv.w, 0.f);
    kv.x = a * a; kv.y = b * b; kv.z = c * c; kv.w = d * d;
    ((float4*)k)[i] = kv;
}

// ---------------- TF32 GEMM: C[m,n] = sum_k A[m,k] * W[n,k] ------------------
// M=16384, N=2048, K=2048. Block tile 128x128x32, 8 warps, warp tile 32x64.
// SMEM: [A|B] x 2 stages, row stride 36 floats -> conflict-free fragment LDS.
// EPI 0: C = acc
// EPI 1: C = aux + acc                      (residual add of x)
// EPI 2: C = C + sigmoid(aux) * acc         (final channel-mix gate, in-place)

#define GSTR 36   // smem row stride in floats (36*4 = 144B, 16B aligned)

__device__ __forceinline__ void gemm_issue(
    const float* __restrict__ Abase, const float* __restrict__ Wbase,
    float* Asb, float* Bsb, int kofs, int tid)
{
    #pragma unroll
    for (int j = 0; j < 4; j++) {
        int ch = tid + j * 256;
        int r  = ch >> 3;
        int k4 = (ch & 7) * 4;
        cp_async16(smem_u32(Asb + r * GSTR + k4), Abase + (size_t)r * 2048 + kofs + k4);
        cp_async16(smem_u32(Bsb + r * GSTR + k4), Wbase + (size_t)r * 2048 + kofs + k4);
    }
    asm volatile("cp.async.commit_group;\n" ::: "memory");
}

template<int EPI>
__global__ __launch_bounds__(256) void gemm_kernel(
    const float* __restrict__ A, const float* __restrict__ W,
    float* __restrict__ C, const float* __restrict__ aux)
{
    extern __shared__ float smem[];
    float* As = smem;                     // 2 stages * 128*GSTR
    float* Bs = smem + 2 * 128 * GSTR;

    int tid  = threadIdx.x;
    int lane = tid & 31;
    int wid  = tid >> 5;
    int bm = blockIdx.y * 128;
    int bn = blockIdx.x * 128;
    int mwarp = (wid & 3) * 32;
    int nwarp = (wid >> 2) * 64;

    const float* Abase = A + (size_t)bm * 2048;
    const float* Wbase = W + (size_t)bn * 2048;

    float acc[2][8][4];
    #pragma unroll
    for (int i = 0; i < 2; i++)
        #pragma unroll
        for (int j = 0; j < 8; j++)
            #pragma unroll
            for (int q = 0; q < 4; q++) acc[i][j][q] = 0.f;

    gemm_issue(Abase, Wbase, As, Bs, 0, tid);

    const int NC = 2048 / 32;   // 64 k-chunks
    for (int c = 0; c < NC; c++) {
        int buf = c & 1;
        if (c + 1 < NC) {
            gemm_issue(Abase, Wbase,
                       As + (buf ^ 1) * 128 * GSTR,
                       Bs + (buf ^ 1) * 128 * GSTR,
                       (c + 1) * 32, tid);
            asm volatile("cp.async.wait_group 1;\n" ::: "memory");
        } else {
            asm volatile("cp.async.wait_group 0;\n" ::: "memory");
        }
        __syncthreads();

        const float* Asb = As + buf * 128 * GSTR;
        const float* Bsb = Bs + buf * 128 * GSTR;

        #pragma unroll
        for (int ks = 0; ks < 4; ks++) {
            int k0 = ks * 8 + (lane & 3);
            uint32_t a[2][4];
            #pragma unroll
            for (int mt = 0; mt < 2; mt++) {
                const float* p = Asb + (mwarp + mt * 16 + (lane >> 2)) * GSTR + k0;
                a[mt][0] = __float_as_uint(p[0]);
                a[mt][1] = __float_as_uint(p[8 * GSTR]);
                a[mt][2] = __float_as_uint(p[4]);
                a[mt][3] = __float_as_uint(p[8 * GSTR + 4]);
            }
            #pragma unroll
            for (int nt = 0; nt < 8; nt++) {
                const float* p = Bsb + (nwarp + nt * 8 + (lane >> 2)) * GSTR + k0;
                uint32_t b0 = __float_as_uint(p[0]);
                uint32_t b1 = __float_as_uint(p[4]);
                #pragma unroll
                for (int mt = 0; mt < 2; mt++) {
                    asm volatile(
                        "mma.sync.aligned.m16n8k8.row.col.f32.tf32.tf32.f32 "
                        "{%0,%1,%2,%3},{%4,%5,%6,%7},{%8,%9},{%0,%1,%2,%3};\n"
                        : "+f"(acc[mt][nt][0]), "+f"(acc[mt][nt][1]),
                          "+f"(acc[mt][nt][2]), "+f"(acc[mt][nt][3])
                        : "r"(a[mt][0]), "r"(a[mt][1]), "r"(a[mt][2]), "r"(a[mt][3]),
                          "r"(b0), "r"(b1));
                }
            }
        }
        __syncthreads();
    }

    // ---------------- epilogue ----------------
    int rbase = bm + mwarp + (lane >> 2);
    int cbase = bn + nwarp + (lane & 3) * 2;
    #pragma unroll
    for (int mt = 0; mt < 2; mt++) {
        #pragma unroll
        for (int nt = 0; nt < 8; nt++) {
            int r0 = rbase + mt * 16;
            int cc = cbase + nt * 8;
            size_t i0 = (size_t)r0 * 2048 + cc;
            size_t i1 = i0 + (size_t)8 * 2048;
            float v0 = acc[mt][nt][0], v1 = acc[mt][nt][1];
            float v2 = acc[mt][nt][2], v3 = acc[mt][nt][3];
            if (EPI == 0) {
                C[i0] = v0;  C[i0 + 1] = v1;
                C[i1] = v2;  C[i1 + 1] = v3;
            } else if (EPI == 1) {
                C[i0] = aux[i0] + v0;          C[i0 + 1] = aux[i0 + 1] + v1;
                C[i1] = aux[i1] + v2;          C[i1 + 1] = aux[i1 + 1] + v3;
            } else {
                C[i0]     = C[i0]     + sigmoidf_(aux[i0])     * v0;
                C[i0 + 1] = C[i0 + 1] + sigmoidf_(aux[i0 + 1]) * v1;
                C[i1]     = C[i1]     + sigmoidf_(aux[i1])     * v2;
                C[i1 + 1] = C[i1 + 1] + sigmoidf_(aux[i1 + 1]) * v3;
            }
        }
    }
}

// ---------------- host orchestration -----------------------------------------
extern "C" void kernel_launch(void* const* d_in, const int* in_sizes, int n_in,
                              void* d_out, int out_size)
{
    const float* x    = (const float*)d_in[0];
    const float* ln1g = (const float*)d_in[1];
    const float* ln1b = (const float*)d_in[2];
    const float* ln2g = (const float*)d_in[3];
    const float* ln2b = (const float*)d_in[4];
    // d_in[5] = tm_w (unused by the reference semantics)
    const float* tmu  = (const float*)d_in[6];
    const float* tmur = (const float*)d_in[7];
    const float* tmuk = (const float*)d_in[8];
    const float* tmuv = (const float*)d_in[9];
    const float* tWr  = (const float*)d_in[10];
    const float* tWk  = (const float*)d_in[11];
    const float* tWv  = (const float*)d_in[12];
    const float* tWo  = (const float*)d_in[13];
    const float* cmur = (const float*)d_in[14];
    const float* cmuk = (const float*)d_in[15];
    const float* cWr  = (const float*)d_in[16];
    const float* cWk  = (const float*)d_in[17];
    const float* cWv  = (const float*)d_in[18];
    float* out = (float*)d_out;

    float *h, *xr, *xk, *xv, *rr, *kk, *vv;
    cudaGetSymbolAddress((void**)&h,  g_h);
    cudaGetSymbolAddress((void**)&xr, g_xr);
    cudaGetSymbolAddress((void**)&xk, g_xk);
    cudaGetSymbolAddress((void**)&xv, g_xv);
    cudaGetSymbolAddress((void**)&rr, g_r);
    cudaGetSymbolAddress((void**)&kk, g_k);
    cudaGetSymbolAddress((void**)&vv, g_v);

    const int SMEM = 4 * 128 * GSTR * 4;   // 73728 B (2 stages A + B)
    cudaFuncSetAttribute(gemm_kernel<0>, cudaFuncAttributeMaxDynamicSharedMemorySize, SMEM);
    cudaFuncSetAttribute(gemm_kernel<1>, cudaFuncAttributeMaxDynamicSharedMemorySize, SMEM);
    cudaFuncSetAttribute(gemm_kernel<2>, cudaFuncAttributeMaxDynamicSharedMemorySize, SMEM);

    dim3 gg(16, 128);         // N tiles x M tiles
    const int EW = 32768;     // (16384*2048/4) / 256

    // ---- time mixing ----
    ln_kernel  <<<MROWS, 256>>>(x, ln1g, ln1b, h);
    mix3_kernel<<<EW, 256>>>(h, tmur, tmuk, tmuv, xr, xk, xv);
    gemm_kernel<0><<<gg, 256, SMEM>>>(xr, tWr, rr, nullptr);
    gemm_kernel<0><<<gg, 256, SMEM>>>(xk, tWk, kk, nullptr);
    gemm_kernel<0><<<gg, 256, SMEM>>>(xv, tWv, vv, nullptr);
    wkv_kernel <<<EW, 256>>>(rr, kk, vv, tmu, xr);          // z -> xr
    gemm_kernel<1><<<gg, 256, SMEM>>>(xr, tWo, out, x);     // x2 = x + z@Wout^T

    // ---- channel mixing ----
    ln_kernel  <<<MROWS, 256>>>(out, ln2g, ln2b, h);
    mix2_kernel<<<EW, 256>>>(h, cmur, cmuk, xr, xk);
    gemm_kernel<0><<<gg, 256, SMEM>>>(xr, cWr, rr, nullptr);  // r2 pre-sigmoid
    gemm_kernel<0><<<gg, 256, SMEM>>>(xk, cWk, kk, nullptr);  // k2 pre-relu^2
    relusq_kernel<<<EW, 256>>>(kk);
    gemm_kernel<2><<<gg, 256, SMEM>>>(kk, cWv, out, rr);      // out = x2 + sig(r2)*acc
}